// round 3
// baseline (speedup 1.0000x reference)
#include <cuda_runtime.h>

#define NB 2048
#define NT 128
#define NS 256
#define NH 64
#define NE 32
#define NV 29

// ---------------- precomputed constants (filled by setup_kernel) ----------------
__device__ float g_wT[128 * 256];   // [k][j]: k<64 -> W_ih[j][32+k] (context), k>=64 -> W_hh[j][k-64] (h)
__device__ float g_lut[NV * 256];   // [v][j] = b_ih[j]+b_hh[j]+sum_e emb[v][e]*W_ih[j][e]
__device__ float g_fcP[128 * 32];   // [k][v]: xc order [context(0..63), h_new(64..127)]; v>=29 -> 0
__device__ float g_fcb[32];

__device__ __forceinline__ float sigf(float x) {
    return __fdividef(1.0f, 1.0f + __expf(-x));
}
__device__ __forceinline__ float tanhfast(float x) {
    // 1 - 2/(exp(2x)+1): saturates cleanly to +-1, no inf/inf
    return 1.0f - __fdividef(2.0f, __expf(2.0f * x) + 1.0f);
}

__global__ void setup_kernel(const float* __restrict__ emb, const float* __restrict__ W_ih,
                             const float* __restrict__ W_hh, const float* __restrict__ b_ih,
                             const float* __restrict__ b_hh, const float* __restrict__ fc_W,
                             const float* __restrict__ fc_b) {
    const int t = threadIdx.x;
    const int blk = blockIdx.x;
    if (blk < NV) {
        // token LUT row
        float s = b_ih[t] + b_hh[t];
#pragma unroll
        for (int e = 0; e < NE; e++) s += emb[blk * NE + e] * W_ih[t * (NE + NH) + e];
        g_lut[blk * 256 + t] = s;
    } else if (blk == NV) {
        // transposed gate weights
        for (int k = 0; k < 128; k++)
            g_wT[k * 256 + t] = (k < 64) ? W_ih[t * (NE + NH) + NE + k]
                                         : W_hh[t * NH + (k - 64)];
    } else {
        // fc weights permuted to xc order [context, h_new], padded to 32 outputs
        for (int idx = t; idx < 4096; idx += 256) {
            const int k = idx >> 5, v = idx & 31;
            float val = 0.0f;
            if (v < NV) val = (k < 64) ? fc_W[v * 128 + 64 + k] : fc_W[v * 128 + (k - 64)];
            g_fcP[idx] = val;
        }
        if (t < 32) g_fcb[t] = (t < NV) ? fc_b[t] : 0.0f;
    }
}

// ---------------- smem layout (offsets in floats) ----------------
#define OFF_ENC   0        // 256 rows * 68 floats = 17408
#define OFF_FCP   17408    // 4096
#define OFF_XC    21504    // 128  [context(0..63) | h(64..127)], 16B aligned
#define OFF_CST   21632    // 64
#define OFF_GATES 21696    // 256
#define OFF_E     21952    // 256  (unnormalized softmax weights)
#define OFF_CPART 22208    // 256
#define OFF_LPART 22464    // 256
#define OFF_WMAX  22720    // 8
#define OFF_WSUM  22728    // 8
#define OFF_FCB   22736    // 32
#define OFF_Y     22768    // 128 ints
#define SMEM_FLOATS 22896
#define SMEM_BYTES (SMEM_FLOATS * 4)   // 91584

__global__ void __launch_bounds__(256, 1)
decoder_kernel(const int* __restrict__ y, const float* __restrict__ h0,
               const float* __restrict__ c0, const float* __restrict__ enc,
               float* __restrict__ out) {
    extern __shared__ float sm[];
    float* sEnc   = sm + OFF_ENC;
    float* sFcP   = sm + OFF_FCP;
    float* sXc    = sm + OFF_XC;
    float* sCst   = sm + OFF_CST;
    float* sGates = sm + OFF_GATES;
    float* sE     = sm + OFF_E;
    float* sCpart = sm + OFF_CPART;
    float* sLpart = sm + OFF_LPART;
    float* sWmax  = sm + OFF_WMAX;
    float* sWsum  = sm + OFF_WSUM;
    float* sFcb   = sm + OFF_FCB;
    int*   sY     = (int*)(sm + OFF_Y);

    const int b = blockIdx.x, tid = threadIdx.x;
    const int lane = tid & 31, warp = tid >> 5;

    // one-time loads: encoder row [256x64] -> padded smem (row stride 68)
    const float* encb = enc + (size_t)b * (NS * NH);
    for (int idx = tid; idx < NS * NH; idx += 256) {
        const int s = idx >> 6, h = idx & 63;
        sEnc[s * 68 + h] = encb[idx];
    }
    for (int idx = tid; idx < 4096; idx += 256) sFcP[idx] = g_fcP[idx];
    if (tid < 64) { sXc[64 + tid] = h0[b * 64 + tid]; sCst[tid] = c0[b * 64 + tid]; }
    if (tid < 128) sY[tid] = y[b * 128 + tid];
    if (tid < 32) sFcb[tid] = g_fcb[tid];

    // per-thread gate weight column in registers
    float w[128];
#pragma unroll
    for (int k = 0; k < 128; k++) w[k] = g_wT[k * 256 + tid];
    __syncthreads();

    const float4* erow = (const float4*)(sEnc + tid * 68);
    const int ch_s0 = (tid >> 6) << 6;   // context chunk: 4 chunks x 64 s
    const int ch_h  = tid & 63;
    const int lk0   = (tid >> 5) << 4;   // logits chunk: 8 chunks x 16 k
    const int lv    = tid & 31;

    for (int t = 0; t < NT; t++) {
        const float lg = g_lut[sY[t] * 256 + tid];  // early L2 load, used in gates phase

        // ---- scores: s = tid, dot(enc_row, h) ----
        const float4* hv4 = (const float4*)(sXc + 64);
        float4 a4 = make_float4(0.f, 0.f, 0.f, 0.f);
#pragma unroll
        for (int i = 0; i < 16; i++) {
            const float4 e4 = erow[i];
            const float4 h4 = hv4[i];
            a4.x = fmaf(e4.x, h4.x, a4.x); a4.y = fmaf(e4.y, h4.y, a4.y);
            a4.z = fmaf(e4.z, h4.z, a4.z); a4.w = fmaf(e4.w, h4.w, a4.w);
        }
        const float sc = (a4.x + a4.y) + (a4.z + a4.w);

        // ---- block max ----
        float m = sc;
#pragma unroll
        for (int o = 16; o > 0; o >>= 1) m = fmaxf(m, __shfl_xor_sync(0xffffffffu, m, o));
        if (lane == 0) sWmax[warp] = m;
        __syncthreads();
        float gm = sWmax[0];
#pragma unroll
        for (int i = 1; i < 8; i++) gm = fmaxf(gm, sWmax[i]);

        // ---- exp + block sum ----
        const float ev = __expf(sc - gm);
        sE[tid] = ev;
        float ss = ev;
#pragma unroll
        for (int o = 16; o > 0; o >>= 1) ss += __shfl_xor_sync(0xffffffffu, ss, o);
        if (lane == 0) sWsum[warp] = ss;
        __syncthreads();
        float sumE = sWsum[0];
#pragma unroll
        for (int i = 1; i < 8; i++) sumE += sWsum[i];

        // ---- context partials: chunk over s, thread owns one h ----
        float cp = 0.f;
        const float4* ev4 = (const float4*)(sE + ch_s0);
        const float* ebase = sEnc + ch_s0 * 68 + ch_h;
#pragma unroll
        for (int i = 0; i < 16; i++) {
            const float4 e4 = ev4[i];
            const float* p = ebase + i * 272;   // 4 rows * 68
            cp = fmaf(e4.x, p[0],   cp);
            cp = fmaf(e4.y, p[68],  cp);
            cp = fmaf(e4.z, p[136], cp);
            cp = fmaf(e4.w, p[204], cp);
        }
        sCpart[tid] = cp;
        __syncthreads();
        if (tid < 64) {
            const float cx = (sCpart[tid] + sCpart[64 + tid]) +
                             (sCpart[128 + tid] + sCpart[192 + tid]);
            sXc[tid] = cx * __fdividef(1.0f, sumE);
        }
        __syncthreads();

        // ---- gates: g[j] = lut + sum_k xc[k]*w[k][j] ----
        float g = lg;
        const float4* xc4 = (const float4*)sXc;
#pragma unroll
        for (int i = 0; i < 32; i++) {
            const float4 x4 = xc4[i];
            g = fmaf(x4.x, w[4 * i],     g);
            g = fmaf(x4.y, w[4 * i + 1], g);
            g = fmaf(x4.z, w[4 * i + 2], g);
            g = fmaf(x4.w, w[4 * i + 3], g);
        }
        sGates[tid] = g;
        __syncthreads();

        // ---- LSTM cell update (i, f, g, o order) ----
        if (tid < 64) {
            const float gi = sGates[tid],        gf = sGates[64 + tid];
            const float gg = sGates[128 + tid],  go = sGates[192 + tid];
            const float cn = sigf(gf) * sCst[tid] + sigf(gi) * tanhfast(gg);
            const float hn = sigf(go) * tanhfast(cn);
            sCst[tid] = cn;
            sXc[64 + tid] = hn;
        }
        __syncthreads();

        // ---- logits partials: combined=[h_new, context] handled via permuted fcP ----
        float lp = 0.f;
        const float4* x4p = (const float4*)(sXc + lk0);
#pragma unroll
        for (int i = 0; i < 4; i++) {
            const float4 x4 = x4p[i];
            const float* fp = sFcP + (lk0 + 4 * i) * 32 + lv;
            lp = fmaf(x4.x, fp[0],  lp);
            lp = fmaf(x4.y, fp[32], lp);
            lp = fmaf(x4.z, fp[64], lp);
            lp = fmaf(x4.w, fp[96], lp);
        }
        sLpart[tid] = lp;
        __syncthreads();

        if (tid < NV) {
            float r = sFcb[tid];
#pragma unroll
            for (int c = 0; c < 8; c++) r += sLpart[c * 32 + tid];
            out[((size_t)b * NT + t) * NV + tid] = r;
        }
        // no trailing barrier: next write to sLpart/sE/sWmax is separated from
        // this step's reads by >=1 of the 7 per-step barriers above
    }
}

extern "C" void kernel_launch(void* const* d_in, const int* in_sizes, int n_in,
                              void* d_out, int out_size) {
    const int*   y      = (const int*)d_in[0];
    const float* h0     = (const float*)d_in[1];
    const float* c0     = (const float*)d_in[2];
    const float* encout = (const float*)d_in[3];
    const float* emb    = (const float*)d_in[4];
    const float* W_ih   = (const float*)d_in[5];
    const float* W_hh   = (const float*)d_in[6];
    const float* b_ih   = (const float*)d_in[7];
    const float* b_hh   = (const float*)d_in[8];
    const float* fc_W   = (const float*)d_in[9];
    const float* fc_b   = (const float*)d_in[10];
    float* out = (float*)d_out;

    cudaFuncSetAttribute(decoder_kernel, cudaFuncAttributeMaxDynamicSharedMemorySize, SMEM_BYTES);

    setup_kernel<<<NV + 2, 256>>>(emb, W_ih, W_hh, b_ih, b_hh, fc_W, fc_b);
    decoder_kernel<<<NB, 256, SMEM_BYTES>>>(y, h0, c0, encout, out);
}